// round 15
// baseline (speedup 1.0000x reference)
#include <cuda_runtime.h>
#include <cuda_bf16.h>

#define DEPTH        4096
#define NTHREADS     256     /* one thread per 16 samples per row */
#define ROWS_PER_CTA 8
#define HKC          0.70710678118654752440f

// 256-thread / 16-samples-per-thread wavelet layer, R7 pipeline structure.
// 4 CTAs per SM (vs 2 at 512 threads) -> 4 independent barrier domains, so
// barrier waits of one CTA are covered by three others instead of one.
// Persistent registers: 16 perm indices only; vec_b/vec_g/vec_s are L1-hot
// per-row reloads. One-row x prefetch into the freed x registers.
//
// Reference slice map (reproduced exactly, incl. overlapping slices):
//   coeff_lst = [ g[0:256], g[2048:2304], g[1024:1536], g[512:1536], g[256:2304] ]
__global__ __launch_bounds__(NTHREADS, 4)
void wavelet_fused_kernel(const float* __restrict__ x,
                          const float* __restrict__ vec_b,
                          const float* __restrict__ vec_g,
                          const float* __restrict__ vec_s,
                          const int*  __restrict__ perm,
                          float* __restrict__ out)
{
    __shared__ float c[2][DEPTH];                 // 32 KB double buffer

    const int t = threadIdx.x;                    // 0..255, owns samples 16t..16t+15

    // ---- persistent: 16 perm indices ------------------------------------
    const int  p0  = __ldg(&perm[t]);
    const int  p1  = __ldg(&perm[2048 + t]);
    const int2 p2  = __ldg(reinterpret_cast<const int2*>(&perm[1024 + 2 * t]));
    const int4 p3  = __ldg(reinterpret_cast<const int4*>(&perm[512  + 4 * t]));
    const int4 p4a = __ldg(reinterpret_cast<const int4*>(&perm[256  + 8 * t]));
    const int4 p4b = __ldg(reinterpret_cast<const int4*>(&perm[256  + 8 * t + 4]));

    const float H2 = HKC * HKC;
    const float H3 = H2 * HKC;
    const float H4 = H2 * H2;

    const size_t base = (size_t)blockIdx.x * ROWS_PER_CTA * DEPTH;
    const float4* x4  = reinterpret_cast<const float4*>(x + base) + 4 * t;
    float4*       o4  = reinterpret_cast<float4*>(out + base) + 4 * t;
    const float4* bp4 = reinterpret_cast<const float4*>(vec_b) + 4 * t;
    const float4* sp4 = reinterpret_cast<const float4*>(vec_s) + 4 * t;

    // preload row 0
    float4 xv0 = __ldcs(&x4[0]);
    float4 xv1 = __ldcs(&x4[1]);
    float4 xv2 = __ldcs(&x4[2]);
    float4 xv3 = __ldcs(&x4[3]);

    #pragma unroll 1
    for (int r = 0; r < ROWS_PER_CTA; ++r) {
        float* cb = c[r & 1];

        // ---- y = x * vec_b (bv reloaded, L1-hot) -------------------------
        const float4 bv0 = __ldg(&bp4[0]);
        const float4 bv1 = __ldg(&bp4[1]);
        const float4 bv2 = __ldg(&bp4[2]);
        const float4 bv3 = __ldg(&bp4[3]);
        float y[16];
        y[0]  = xv0.x * bv0.x;  y[1]  = xv0.y * bv0.y;
        y[2]  = xv0.z * bv0.z;  y[3]  = xv0.w * bv0.w;
        y[4]  = xv1.x * bv1.x;  y[5]  = xv1.y * bv1.y;
        y[6]  = xv1.z * bv1.z;  y[7]  = xv1.w * bv1.w;
        y[8]  = xv2.x * bv2.x;  y[9]  = xv2.y * bv2.y;
        y[10] = xv2.z * bv2.z;  y[11] = xv2.w * bv2.w;
        y[12] = xv3.x * bv3.x;  y[13] = xv3.y * bv3.y;
        y[14] = xv3.z * bv3.z;  y[15] = xv3.w * bv3.w;

        // ---- prefetch row r+1 into the freed x registers -----------------
        if (r + 1 < ROWS_PER_CTA) {
            const float4* xn = x4 + (size_t)(r + 1) * (DEPTH / 4);
            xv0 = __ldcs(&xn[0]);
            xv1 = __ldcs(&xn[1]);
            xv2 = __ldcs(&xn[2]);
            xv3 = __ldcs(&xn[3]);
        }

        // ---- 4-scale Haar butterfly in registers -------------------------
        float s1[8], d1[8];
        #pragma unroll
        for (int p = 0; p < 8; ++p) {
            s1[p] = y[2*p] + y[2*p+1];
            d1[p] = (y[2*p] - y[2*p+1]) * HKC;
        }
        float s2[4], d2[4];
        #pragma unroll
        for (int q = 0; q < 4; ++q) {
            s2[q] = s1[2*q] + s1[2*q+1];
            d2[q] = (s1[2*q] - s1[2*q+1]) * H2;
        }
        float s3[2], d3[2];
        #pragma unroll
        for (int u = 0; u < 2; ++u) {
            s3[u] = s2[2*u] + s2[2*u+1];
            d3[u] = (s2[2*u] - s2[2*u+1]) * H3;
        }
        // c = [cA4(256) | d4(256) | d3(512) | d2(1024) | d1(2048)]
        cb[t]       = (s3[0] + s3[1]) * H4;
        cb[256 + t] = (s3[0] - s3[1]) * H4;
        *reinterpret_cast<float2*>(&cb[512  + 2*t]) = make_float2(d3[0], d3[1]);
        *reinterpret_cast<float4*>(&cb[1024 + 4*t]) = make_float4(d2[0], d2[1], d2[2], d2[3]);
        *reinterpret_cast<float4*>(&cb[2048 + 8*t]) = make_float4(d1[0], d1[1], d1[2], d1[3]);
        *reinterpret_cast<float4*>(&cb[2048 + 8*t + 4]) = make_float4(d1[4], d1[5], d1[6], d1[7]);

        __syncthreads();

        // ---- gather (16 random LDS) + weights (L1-hot reloads) -----------
        const float  w0  = __ldg(&vec_g[t]);
        const float  w1  = __ldg(&vec_g[2048 + t]);
        const float2 w2  = __ldg(reinterpret_cast<const float2*>(&vec_g[1024 + 2*t]));
        const float4 w3  = __ldg(reinterpret_cast<const float4*>(&vec_g[512  + 4*t]));
        const float4 w4a = __ldg(reinterpret_cast<const float4*>(&vec_g[256  + 8*t]));
        const float4 w4b = __ldg(reinterpret_cast<const float4*>(&vec_g[256  + 8*t + 4]));

        const float G0 = w0 * cb[p0];
        const float G1 = w1 * cb[p1];
        float G2[2], G3[4], G4[8];
        G2[0] = w2.x * cb[p2.x];  G2[1] = w2.y * cb[p2.y];
        G3[0] = w3.x * cb[p3.x];  G3[1] = w3.y * cb[p3.y];
        G3[2] = w3.z * cb[p3.z];  G3[3] = w3.w * cb[p3.w];
        G4[0] = w4a.x * cb[p4a.x];  G4[1] = w4a.y * cb[p4a.y];
        G4[2] = w4a.z * cb[p4a.z];  G4[3] = w4a.w * cb[p4a.w];
        G4[4] = w4b.x * cb[p4b.x];  G4[5] = w4b.y * cb[p4b.y];
        G4[6] = w4b.z * cb[p4b.z];  G4[7] = w4b.w * cb[p4b.w];

        // ---- inverse butterfly -------------------------------------------
        const float u1p = (G0 + G1) * HKC;
        const float u1m = (G0 - G1) * HKC;
        float u2[4];
        u2[0] = (u1p + G2[0]) * HKC;  u2[1] = (u1p - G2[0]) * HKC;
        u2[2] = (u1m + G2[1]) * HKC;  u2[3] = (u1m - G2[1]) * HKC;
        float u3[8];
        #pragma unroll
        for (int j = 0; j < 8; ++j) {
            const float g = G3[j >> 1];
            u3[j] = (u2[j >> 1] + ((j & 1) ? -g : g)) * HKC;
        }

        // ---- scale by vec_s (reload) + store -----------------------------
        float4* orow = o4 + (size_t)r * (DEPTH / 4);
        #pragma unroll
        for (int j = 0; j < 4; ++j) {
            const float4 sv = __ldg(&sp4[j]);
            const int k0 = 4 * j;
            float4 ov;
            ov.x = (u3[(k0+0) >> 1] + G4[(k0+0) >> 1]) * HKC * sv.x;
            ov.y = (u3[(k0+1) >> 1] - G4[(k0+1) >> 1]) * HKC * sv.y;
            ov.z = (u3[(k0+2) >> 1] + G4[(k0+2) >> 1]) * HKC * sv.z;
            ov.w = (u3[(k0+3) >> 1] - G4[(k0+3) >> 1]) * HKC * sv.w;
            __stcs(&orow[j], ov);
        }
        // no trailing sync: double buffer + next row's sync protects reuse
    }
}

extern "C" void kernel_launch(void* const* d_in, const int* in_sizes, int n_in,
                              void* d_out, int out_size)
{
    const float* x     = (const float*)d_in[0];
    const float* vec_b = (const float*)d_in[1];
    const float* vec_g = (const float*)d_in[2];
    const float* vec_s = (const float*)d_in[3];
    const int*   perm  = (const int*)  d_in[4];
    float* out = (float*)d_out;

    const int batch = in_sizes[0] / DEPTH;            // 8192
    wavelet_fused_kernel<<<batch / ROWS_PER_CTA, NTHREADS>>>(x, vec_b, vec_g, vec_s, perm, out);
}